// round 12
// baseline (speedup 1.0000x reference)
#include <cuda_runtime.h>

#define NP     16384
#define CIN    128
#define COUT   256
#define KK     20
#define WCOLS  512
#define QPB    8
#define NSLICE 8         /* candidate slices for the filter kernel */
#define KTP    1024      /* pairs per slice tile -> 2048 candidates, 32KB smem */
#define SUBCAP 128       /* survivor entries per (query, slice) */
#define PADROWS 2048     /* physical pad so slice-7 overflow stays in bounds */

// ---- scratch (no allocations allowed: __device__ globals) ----
__device__ float4 g_cand[NP];          // {x,y,z,|p|^2/2}
__device__ float4 g_A[NP/2];           // pair-SoA {x0,x1,y0,y1}
__device__ float4 g_B[NP/2];           // pair-SoA {z0,z1,-w0,-w1}
__device__ float  g_thr1[NP];          // lower bound on global 21st-best score
__device__ int    g_cntS[NSLICE * NP]; // survivor count per (slice, query)
// (score<<32|idx), lane-interleaved; padded: slice-s overflow spills into
// slice-(s+1) rows OF THE SAME QUERY (detected via cnt>SUBCAP -> exact fallback)
__device__ unsigned long long g_buf[(size_t)(NSLICE*SUBCAP + PADROWS) * NP];
__device__ int    g_knn[NP * KK];
__device__ float  g_W2[CIN * WCOLS];
__device__ float  g_AB[(size_t)NP * WCOLS];   // [:,0:256)=A(+bias), [:,256:512)=B
__device__ float  g_sel[(size_t)NP * COUT];
__device__ double g_sumD[COUT];
__device__ double g_sumsqD[COUT];
__device__ float  g_scale[COUT];
__device__ float  g_shift[COUT];

// ---------- packed f32x2 helpers ----------
__device__ __forceinline__ unsigned long long ffma2(unsigned long long a,
                                                    unsigned long long b,
                                                    unsigned long long c) {
    unsigned long long d;
    asm("fma.rn.f32x2 %0, %1, %2, %3;" : "=l"(d) : "l"(a), "l"(b), "l"(c));
    return d;
}
__device__ __forceinline__ unsigned long long bcast2(float x) {
    unsigned long long r;
    asm("mov.b64 %0, {%1, %1};" : "=l"(r) : "f"(x));
    return r;
}
__device__ __forceinline__ void unpack2(unsigned long long v, float& lo, float& hi) {
    asm("mov.b64 {%0, %1}, %2;" : "=f"(lo), "=f"(hi) : "l"(v));
}
__device__ __forceinline__ unsigned long long d_as_ll(double d) {
    return __double_as_longlong(d);
}

// sorted-ascending merge-inserts (drop current min); branchless
__device__ __forceinline__ void merge21(float (&ss)[21], float sv) {
#pragma unroll
    for (int t = 0; t < 20; t++) ss[t] = fmaxf(ss[t], fminf(sv, ss[t+1]));
    ss[20] = fmaxf(ss[20], sv);
}
__device__ __forceinline__ void merge22(float (&ss)[22], float sv) {
#pragma unroll
    for (int t = 0; t < 21; t++) ss[t] = fmaxf(ss[t], fminf(sv, ss[t+1]));
    ss[21] = fmaxf(ss[21], sv);
}

// 8 scores (4 packed pairs) from smem tiles
__device__ __forceinline__ void score8(float* s, const double2* tA, const double2* tB, int p,
                                       unsigned long long mx, unsigned long long my,
                                       unsigned long long mz) {
#pragma unroll
    for (int w = 0; w < 4; w++) {
        double2 a = tA[p + w];
        double2 b = tB[p + w];
        unsigned long long t0 = ffma2(mz, d_as_ll(b.x), d_as_ll(b.y));  // z*mz - w
        t0 = ffma2(my, d_as_ll(a.y), t0);
        t0 = ffma2(mx, d_as_ll(a.x), t0);
        unpack2(t0, s[2*w], s[2*w+1]);
    }
}

// scalar score, identical rounding to the packed path
__device__ __forceinline__ float scoreQ(const float4& me, const float4& c) {
    return fmaf(me.x, c.x, fmaf(me.y, c.y, fmaf(me.z, c.z, -c.w)));
}

__device__ __forceinline__ unsigned long long packSI(float s, int j) {
    return ((unsigned long long)__float_as_uint(s) << 32) | (unsigned)j;
}
__device__ __forceinline__ float scoreOf(unsigned long long e) {
    return __uint_as_float((unsigned)(e >> 32));
}
__device__ __forceinline__ int idxOf(unsigned long long e) {
    return (int)(e & 0xffffffffu);
}

// ---- prep: candidates (AoS + pair-SoA), W rearrange, stat zeroing ----
__global__ void prep_kernel(const float* __restrict__ pos, const float* __restrict__ W) {
    int t = blockIdx.x * blockDim.x + threadIdx.x;
    if (t < NP) {
        float x = pos[3*t+0], y = pos[3*t+1], z = pos[3*t+2];
        g_cand[t] = make_float4(x, y, z, 0.5f*(x*x + y*y + z*z));
    }
    if (t < NP/2) {
        int j0 = 2*t, j1 = 2*t + 1;
        float x0 = pos[3*j0+0], y0 = pos[3*j0+1], z0 = pos[3*j0+2];
        float x1 = pos[3*j1+0], y1 = pos[3*j1+1], z1 = pos[3*j1+2];
        float w0 = 0.5f*(x0*x0 + y0*y0 + z0*z0);
        float w1 = 0.5f*(x1*x1 + y1*y1 + z1*z1);
        g_A[t] = make_float4(x0, x1, y0, y1);
        g_B[t] = make_float4(z0, z1, -w0, -w1);
    }
    if (t < CIN * WCOLS) {
        int kk = t >> 9;
        int c  = t & 511;
        g_W2[t] = (c < COUT) ? W[kk*COUT + c] : W[(kk + CIN)*COUT + (c - COUT)];
    }
    if (t < COUT) { g_sumD[t] = 0.0; g_sumsqD[t] = 0.0; }
}

// ---- knn threshold: cheap valid lower bound on the global 21st-best score ----
// Over candidates [0,2048): compute 64 chunk-maxes (32 cands each), take the
// 22nd largest. Subset order statistic <= superset order statistic, and the
// extra (22nd) slot absorbs the self-score, so thr1 <= global 21st (excl self).
__global__ void knn_thresh_kernel() {
    __shared__ double2 tA[KTP];
    __shared__ double2 tB[KTP];
    const int q = blockIdx.x * blockDim.x + threadIdx.x;
    const float4 me = g_cand[q];
    const unsigned long long mx = bcast2(me.x), my = bcast2(me.y), mz = bcast2(me.z);
    const float NEG = -3.0e38f;

    for (int l = threadIdx.x; l < KTP; l += blockDim.x) {
        tA[l] = ((const double2*)g_A)[l];
        tB[l] = ((const double2*)g_B)[l];
    }
    __syncthreads();

    float ss[22];
#pragma unroll
    for (int t = 0; t < 22; t++) ss[t] = NEG;

    for (int p = 0; p < KTP; p += 16) {        // 32 candidates per chunk
        float cm = NEG;
#pragma unroll
        for (int o = 0; o < 4; o++) {
            float s[8];
            score8(s, tA, tB, p + 4*o, mx, my, mz);
#pragma unroll
            for (int u = 0; u < 8; u++) cm = fmaxf(cm, s[u]);
        }
        merge22(ss, cm);
    }
    g_thr1[q] = ss[0];
}

// ---- knn filter: candidate-sliced full scan; private sub-buffers, no atomics ----
// Per candidate: FSETP + @P STG.64 + @P pointer bump. NO capacity guard:
// overflow spills into the same query's higher-slice rows (physically padded),
// detected afterwards via cnt>SUBCAP -> that query takes the exact fallback.
__global__ void knn_filter_kernel() {
    __shared__ double2 tA[KTP];
    __shared__ double2 tB[KTP];
    const int q = blockIdx.x * blockDim.x + threadIdx.x;
    const int slice = blockIdx.y;
    const int pb0 = slice * KTP;
    const float4 me = g_cand[q];
    const unsigned long long mx = bcast2(me.x), my = bcast2(me.y), mz = bcast2(me.z);
    const float thr1 = g_thr1[q];

    for (int l = threadIdx.x; l < KTP; l += blockDim.x) {
        tA[l] = ((const double2*)g_A)[pb0 + l];
        tB[l] = ((const double2*)g_B)[pb0 + l];
    }
    __syncthreads();

    unsigned long long* const base = &g_buf[(size_t)(slice * SUBCAP) * NP + q];
    unsigned long long* ptr = base;
    const int jb0 = 2*pb0;
    for (int p = 0; p < KTP; p += 4) {
        float s[8];
        score8(s, tA, tB, p, mx, my, mz);
        const int jb = jb0 + 2*p;
#pragma unroll
        for (int u = 0; u < 8; u++) {
            bool keep = (s[u] > thr1);
            if (keep) *ptr = packSI(s[u], jb + u);   // @P STG.64, unguarded
            ptr += keep ? NP : 0;                    // @P pointer bump
        }
    }
    g_cntS[slice * NP + q] = (int)((ptr - base) / NP);  // >SUBCAP -> ovf flag
}

// ---- knn final: warp-per-slice cooperative exact top-20 ----
// Block: 256 threads = 8 warps x 32 lanes; warp w = slice w, lane = query.
// Phase 1: per-thread local top-22 of its slice (global top-22 incl self is
//          contained in the union of per-slice top-22s).
// Phase 2: slice-0 threads merge 8x22 smem scores -> t21 (21st excl self;
//          self = strict max absorbs the extra slot).
// Phase 3: count survivors > t21 per slice, smem prefix -> disjoint writes.
//          g_knn order is irrelevant (max-pool); ties/overflow -> exact fallback.
__global__ void knn_final_kernel() {
    __shared__ float sS[NSLICE][32][23];    // padded: stride 23 is odd -> no conflicts
    __shared__ int   sCnt[NSLICE][32];
    __shared__ float sT[32];

    const int lane = threadIdx.x & 31;
    const int sl   = threadIdx.x >> 5;
    const int q    = blockIdx.x * 32 + lane;
    const float NEG = -3.0e38f;

    int c = g_cntS[sl * NP + q];
    const bool ovf = (c > SUBCAP);
    if (c > SUBCAP) c = SUBCAP;
    const unsigned long long* myb = &g_buf[(size_t)(sl * SUBCAP) * NP + q];

    float ss[22];
#pragma unroll
    for (int t = 0; t < 22; t++) ss[t] = NEG;
    {
        int m = 0;
        for (; m + 4 <= c; m += 4) {                  // coalesced, MLP=4
            unsigned long long e0 = myb[(m+0) * NP];
            unsigned long long e1 = myb[(m+1) * NP];
            unsigned long long e2 = myb[(m+2) * NP];
            unsigned long long e3 = myb[(m+3) * NP];
            merge22(ss, scoreOf(e0));
            merge22(ss, scoreOf(e1));
            merge22(ss, scoreOf(e2));
            merge22(ss, scoreOf(e3));
        }
        for (; m < c; m++) merge22(ss, scoreOf(myb[m * NP]));
    }
#pragma unroll
    for (int t = 0; t < 22; t++) sS[sl][lane][t] = ss[t];
    __syncthreads();

    // phase 2: slice-0 threads merge the other 7 lists
    if (sl == 0) {
        for (int s2 = 1; s2 < NSLICE; s2++)
#pragma unroll
            for (int t = 0; t < 22; t++) merge22(ss, sS[s2][lane][t]);
        sT[lane] = ss[0];                             // 21st best excluding self
    }
    __syncthreads();
    const float t21 = sT[lane];

    // phase 3: count survivors strictly above t21 in my slice
    int na = 0;
    for (int m = 0; m < c; m++) {
        unsigned long long e = myb[m * NP];
        na += (scoreOf(e) > t21 && idxOf(e) != q) ? 1 : 0;
    }
    if (ovf) na = 1 << 20;                            // force fallback on overflow
    sCnt[sl][lane] = na;
    __syncthreads();

    int pre = 0, total = 0;
    for (int s2 = 0; s2 < NSLICE; s2++) {
        int v = sCnt[s2][lane];
        pre += (s2 < sl) ? v : 0;
        total += v;
    }

    if (total == KK) {                                // common case: exact, no ties
        int o = pre;
        for (int m = 0; m < c; m++) {
            unsigned long long e = myb[m * NP];
            int j = idxOf(e);
            if (scoreOf(e) > t21 && j != q) g_knn[q*KK + (o++)] = j;
        }
    } else if (sl == 0) {                             // P~0: ties or overflow
        const float4 me = g_cand[q];
        float bs[21];
#pragma unroll
        for (int t = 0; t < 21; t++) bs[t] = NEG;
        for (int j = 0; j < NP; j++)
            merge21(bs, (j != q) ? scoreQ(me, g_cand[j]) : NEG);
        float b21 = bs[0];
        int out = 0;
        for (int j = 0; j < NP && out < KK; j++)
            if (j != q && scoreQ(me, g_cand[j]) > b21) g_knn[q*KK + (out++)] = j;
        for (int j = 0; j < NP && out < KK; j++)
            if (j != q && scoreQ(me, g_cand[j]) == b21) g_knn[q*KK + (out++)] = j;
    }
}

// ---- SGEMM: AB[16384,512] = X[16384,128] @ W2[128,512]  (+bias on cols<256) ----
// Inner product via packed fma.rn.f32x2: 32 FFMA2 per k-step instead of 64 FFMA.
__global__ void gemm_kernel(const float* __restrict__ X, const float* __restrict__ bias) {
    __shared__ __align__(16) float As[8][128];
    __shared__ __align__(16) float Bs[8][128];
    const int tid = threadIdx.x;
    const int m0 = blockIdx.y * 128;
    const int n0 = blockIdx.x * 128;
    const int tx = tid & 15;
    const int ty = tid >> 4;
    const int lam = tid >> 1;
    const int lak = (tid & 1) * 4;
    const int lbr = tid >> 5;
    const int lbc = (tid & 31) * 4;

    unsigned long long acc[8][4];
#pragma unroll
    for (int i = 0; i < 8; i++)
#pragma unroll
        for (int j = 0; j < 4; j++) acc[i][j] = 0ull;

    for (int kb = 0; kb < CIN; kb += 8) {
        float4 av = *(const float4*)&X[(size_t)(m0 + lam)*CIN + kb + lak];
        float4 bv = *(const float4*)&g_W2[(kb + lbr)*WCOLS + n0 + lbc];
        __syncthreads();
        As[lak+0][lam] = av.x;
        As[lak+1][lam] = av.y;
        As[lak+2][lam] = av.z;
        As[lak+3][lam] = av.w;
        *(float4*)&Bs[lbr][lbc] = bv;
        __syncthreads();
#pragma unroll
        for (int k = 0; k < 8; k++) {
            float a[8];
            *(float4*)&a[0] = *(const float4*)&As[k][ty*8];
            *(float4*)&a[4] = *(const float4*)&As[k][ty*8 + 4];
            unsigned long long b2[4];
            const unsigned long long* bp = (const unsigned long long*)&Bs[k][tx*8];
            b2[0] = bp[0]; b2[1] = bp[1]; b2[2] = bp[2]; b2[3] = bp[3];
#pragma unroll
            for (int i = 0; i < 8; i++) {
                unsigned long long a2 = bcast2(a[i]);
#pragma unroll
                for (int j = 0; j < 4; j++)
                    acc[i][j] = ffma2(a2, b2[j], acc[i][j]);
            }
        }
    }
    const bool addb = (n0 < COUT);
#pragma unroll
    for (int i = 0; i < 8; i++) {
        int row = m0 + ty*8 + i;
        float r[8];
#pragma unroll
        for (int j = 0; j < 4; j++) unpack2(acc[i][j], r[2*j], r[2*j+1]);
#pragma unroll
        for (int j = 0; j < 8; j += 4) {
            int col = n0 + tx*8 + j;
            float4 v;
            v.x = r[j+0] + (addb ? bias[col+0] : 0.0f);
            v.y = r[j+1] + (addb ? bias[col+1] : 0.0f);
            v.z = r[j+2] + (addb ? bias[col+2] : 0.0f);
            v.w = r[j+3] + (addb ? bias[col+3] : 0.0f);
            *(float4*)&g_AB[(size_t)row*WCOLS + col] = v;
        }
    }
}

// ---- fused edge pass: 2 channels/thread, per (i,c) extreme + channel sum/sumsq ----
__global__ void edge_kernel(const float* __restrict__ gamma) {
    const int c2 = threadIdx.x;            // 0..127 -> channels 2*c2, 2*c2+1
    const int c0 = 2*c2;
    const int i0 = blockIdx.x * QPB;
    const bool uM0 = (gamma[c0]   >= 0.0f);
    const bool uM1 = (gamma[c0+1] >= 0.0f);
    float ps0 = 0.f, ps1 = 0.f, pq0 = 0.f, pq1 = 0.f;
    for (int g = 0; g < QPB; g++) {
        const int i = i0 + g;
        float2 a = *(const float2*)&g_AB[(size_t)i*WCOLS + c0];
        float b0 = uM0 ? -3.0e38f : 3.0e38f;
        float b1 = uM1 ? -3.0e38f : 3.0e38f;
#pragma unroll
        for (int k = 0; k < KK; k++) {
            int j = g_knn[i*KK + k];
            float2 bv = *(const float2*)&g_AB[(size_t)j*WCOLS + COUT + c0];
            float h0 = a.x + bv.x;
            float h1 = a.y + bv.y;
            ps0 += h0; pq0 = fmaf(h0, h0, pq0);
            ps1 += h1; pq1 = fmaf(h1, h1, pq1);
            b0 = uM0 ? fmaxf(b0, h0) : fminf(b0, h0);
            b1 = uM1 ? fmaxf(b1, h1) : fminf(b1, h1);
        }
        *(float2*)&g_sel[(size_t)i*COUT + c0] = make_float2(b0, b1);
    }
    atomicAdd(&g_sumD[c0],     (double)ps0);
    atomicAdd(&g_sumD[c0+1],   (double)ps1);
    atomicAdd(&g_sumsqD[c0],   (double)pq0);
    atomicAdd(&g_sumsqD[c0+1], (double)pq1);
}

// ---- BN stats -> per-channel scale/shift ----
__global__ void finalize_kernel(const float* __restrict__ gamma, const float* __restrict__ beta) {
    int c = threadIdx.x;
    const double inv = 1.0 / (double)(NP * KK);
    double m  = g_sumD[c] * inv;
    double v  = g_sumsqD[c] * inv - m*m;
    float sc = gamma[c] * rsqrtf((float)v + 1e-5f);
    g_scale[c] = sc;
    g_shift[c] = beta[c] - (float)m * sc;
}

// ---- epilogue: normalize selected extreme + LeakyReLU ----
__global__ void out_kernel(float* __restrict__ out) {
    int t = blockIdx.x * blockDim.x + threadIdx.x;
    int c = t & (COUT - 1);
    float h = fmaf(g_sel[t], g_scale[c], g_shift[c]);
    out[t] = (h >= 0.0f) ? h : 0.2f*h;
}

extern "C" void kernel_launch(void* const* d_in, const int* in_sizes, int n_in,
                              void* d_out, int out_size) {
    const float* pos   = (const float*)d_in[0];
    const float* x     = (const float*)d_in[1];
    const float* W     = (const float*)d_in[2];
    const float* b     = (const float*)d_in[3];
    const float* gamma = (const float*)d_in[4];
    const float* beta  = (const float*)d_in[5];
    float* out = (float*)d_out;

    prep_kernel<<<256, 256>>>(pos, W);                         // 0
    knn_thresh_kernel<<<NP / 256, 256>>>();                    // 1
    gemm_kernel<<<dim3(WCOLS / 128, NP / 128), 256>>>(x, b);   // 2
    knn_filter_kernel<<<dim3(NP / 256, NSLICE), 256>>>();      // 3 (ncu slot)
    knn_final_kernel<<<NP / 32, 256>>>();                      // 4
    edge_kernel<<<NP / QPB, 128>>>(gamma);                     // 5
    finalize_kernel<<<1, COUT>>>(gamma, beta);                 // 6
    out_kernel<<<(NP * COUT) / 256, 256>>>(out);               // 7
}

// round 13
// speedup vs baseline: 1.0021x; 1.0021x over previous
#include <cuda_runtime.h>

#define NP     16384
#define CIN    128
#define COUT   256
#define KK     20
#define WCOLS  512
#define QPB    8
#define NSLICE 8         /* candidate slices for the filter kernel */
#define KTP    1024      /* pairs per slice tile -> 2048 candidates, 32KB smem */
#define SUBCAP 128       /* survivor entries per (query, slice) */
#define PADROWS 2048     /* physical pad so slice-7 overflow stays in bounds */

// ---- scratch (no allocations allowed: __device__ globals) ----
__device__ float4 g_cand[NP];          // {x,y,z,|p|^2/2}
__device__ float4 g_A[NP/2];           // pair-SoA {x0,x1,y0,y1}
__device__ float4 g_B[NP/2];           // pair-SoA {z0,z1,-w0,-w1}
__device__ float  g_thr1[NP];          // lower bound on global 21st-best score
__device__ int    g_cntS[NSLICE * NP]; // survivor count per (slice, query)
// (score<<32|idx), lane-interleaved; padded: slice-s overflow spills into
// slice-(s+1) rows OF THE SAME QUERY (detected via cnt>SUBCAP -> exact fallback)
__device__ unsigned long long g_buf[(size_t)(NSLICE*SUBCAP + PADROWS) * NP];
__device__ int    g_knn[NP * KK];
__device__ float  g_W2[CIN * WCOLS];
__device__ float  g_AB[(size_t)NP * WCOLS];   // [:,0:256)=A(+bias), [:,256:512)=B
__device__ float  g_sel[(size_t)NP * COUT];
__device__ double g_sumD[COUT];
__device__ double g_sumsqD[COUT];
__device__ float  g_scale[COUT];
__device__ float  g_shift[COUT];

// ---------- packed f32x2 helpers ----------
__device__ __forceinline__ unsigned long long ffma2(unsigned long long a,
                                                    unsigned long long b,
                                                    unsigned long long c) {
    unsigned long long d;
    asm("fma.rn.f32x2 %0, %1, %2, %3;" : "=l"(d) : "l"(a), "l"(b), "l"(c));
    return d;
}
__device__ __forceinline__ unsigned long long bcast2(float x) {
    unsigned long long r;
    asm("mov.b64 %0, {%1, %1};" : "=l"(r) : "f"(x));
    return r;
}
__device__ __forceinline__ void unpack2(unsigned long long v, float& lo, float& hi) {
    asm("mov.b64 {%0, %1}, %2;" : "=f"(lo), "=f"(hi) : "l"(v));
}
__device__ __forceinline__ unsigned long long d_as_ll(double d) {
    return __double_as_longlong(d);
}

// sorted-ascending merge-inserts (drop current min); branchless
__device__ __forceinline__ void merge21(float (&ss)[21], float sv) {
#pragma unroll
    for (int t = 0; t < 20; t++) ss[t] = fmaxf(ss[t], fminf(sv, ss[t+1]));
    ss[20] = fmaxf(ss[20], sv);
}
__device__ __forceinline__ void merge22(float (&ss)[22], float sv) {
#pragma unroll
    for (int t = 0; t < 21; t++) ss[t] = fmaxf(ss[t], fminf(sv, ss[t+1]));
    ss[21] = fmaxf(ss[21], sv);
}

// 8 scores (4 packed pairs) from smem tiles
__device__ __forceinline__ void score8(float* s, const double2* tA, const double2* tB, int p,
                                       unsigned long long mx, unsigned long long my,
                                       unsigned long long mz) {
#pragma unroll
    for (int w = 0; w < 4; w++) {
        double2 a = tA[p + w];
        double2 b = tB[p + w];
        unsigned long long t0 = ffma2(mz, d_as_ll(b.x), d_as_ll(b.y));  // z*mz - w
        t0 = ffma2(my, d_as_ll(a.y), t0);
        t0 = ffma2(mx, d_as_ll(a.x), t0);
        unpack2(t0, s[2*w], s[2*w+1]);
    }
}

// scalar score, identical rounding to the packed path
__device__ __forceinline__ float scoreQ(const float4& me, const float4& c) {
    return fmaf(me.x, c.x, fmaf(me.y, c.y, fmaf(me.z, c.z, -c.w)));
}

__device__ __forceinline__ unsigned long long packSI(float s, int j) {
    return ((unsigned long long)__float_as_uint(s) << 32) | (unsigned)j;
}
__device__ __forceinline__ float scoreOf(unsigned long long e) {
    return __uint_as_float((unsigned)(e >> 32));
}
__device__ __forceinline__ int idxOf(unsigned long long e) {
    return (int)(e & 0xffffffffu);
}

// ---- prep: candidates (AoS + pair-SoA), W rearrange, stat zeroing ----
__global__ void prep_kernel(const float* __restrict__ pos, const float* __restrict__ W) {
    int t = blockIdx.x * blockDim.x + threadIdx.x;
    if (t < NP) {
        float x = pos[3*t+0], y = pos[3*t+1], z = pos[3*t+2];
        g_cand[t] = make_float4(x, y, z, 0.5f*(x*x + y*y + z*z));
    }
    if (t < NP/2) {
        int j0 = 2*t, j1 = 2*t + 1;
        float x0 = pos[3*j0+0], y0 = pos[3*j0+1], z0 = pos[3*j0+2];
        float x1 = pos[3*j1+0], y1 = pos[3*j1+1], z1 = pos[3*j1+2];
        float w0 = 0.5f*(x0*x0 + y0*y0 + z0*z0);
        float w1 = 0.5f*(x1*x1 + y1*y1 + z1*z1);
        g_A[t] = make_float4(x0, x1, y0, y1);
        g_B[t] = make_float4(z0, z1, -w0, -w1);
    }
    if (t < CIN * WCOLS) {
        int kk = t >> 9;
        int c  = t & 511;
        g_W2[t] = (c < COUT) ? W[kk*COUT + c] : W[(kk + CIN)*COUT + (c - COUT)];
    }
    if (t < COUT) { g_sumD[t] = 0.0; g_sumsqD[t] = 0.0; }
}

// ---- knn threshold: cheap valid lower bound on the global 21st-best score ----
// Over candidates [0,2048): compute 64 chunk-maxes (32 cands each), take the
// 22nd largest. Subset order statistic <= superset order statistic, and the
// extra (22nd) slot absorbs the self-score, so thr1 <= global 21st (excl self).
__global__ void knn_thresh_kernel() {
    __shared__ double2 tA[KTP];
    __shared__ double2 tB[KTP];
    const int q = blockIdx.x * blockDim.x + threadIdx.x;
    const float4 me = g_cand[q];
    const unsigned long long mx = bcast2(me.x), my = bcast2(me.y), mz = bcast2(me.z);
    const float NEG = -3.0e38f;

    for (int l = threadIdx.x; l < KTP; l += blockDim.x) {
        tA[l] = ((const double2*)g_A)[l];
        tB[l] = ((const double2*)g_B)[l];
    }
    __syncthreads();

    float ss[22];
#pragma unroll
    for (int t = 0; t < 22; t++) ss[t] = NEG;

    for (int p = 0; p < KTP; p += 16) {        // 32 candidates per chunk
        float cm = NEG;
#pragma unroll
        for (int o = 0; o < 4; o++) {
            float s[8];
            score8(s, tA, tB, p + 4*o, mx, my, mz);
#pragma unroll
            for (int u = 0; u < 8; u++) cm = fmaxf(cm, s[u]);
        }
        merge22(ss, cm);
    }
    g_thr1[q] = ss[0];
}

// ---- knn filter: candidate-sliced full scan; private sub-buffers, no atomics ----
// Per candidate: FSETP + @P STG.64 + @P pointer bump. NO capacity guard:
// overflow spills into the same query's higher-slice rows (physically padded),
// detected afterwards via cnt>SUBCAP -> that query takes the exact fallback.
__global__ void knn_filter_kernel() {
    __shared__ double2 tA[KTP];
    __shared__ double2 tB[KTP];
    const int q = blockIdx.x * blockDim.x + threadIdx.x;
    const int slice = blockIdx.y;
    const int pb0 = slice * KTP;
    const float4 me = g_cand[q];
    const unsigned long long mx = bcast2(me.x), my = bcast2(me.y), mz = bcast2(me.z);
    const float thr1 = g_thr1[q];

    for (int l = threadIdx.x; l < KTP; l += blockDim.x) {
        tA[l] = ((const double2*)g_A)[pb0 + l];
        tB[l] = ((const double2*)g_B)[pb0 + l];
    }
    __syncthreads();

    unsigned long long* const base = &g_buf[(size_t)(slice * SUBCAP) * NP + q];
    unsigned long long* ptr = base;
    const int jb0 = 2*pb0;
    for (int p = 0; p < KTP; p += 4) {
        float s[8];
        score8(s, tA, tB, p, mx, my, mz);
        const int jb = jb0 + 2*p;
#pragma unroll
        for (int u = 0; u < 8; u++) {
            bool keep = (s[u] > thr1);
            if (keep) *ptr = packSI(s[u], jb + u);   // @P STG.64, unguarded
            ptr += keep ? NP : 0;                    // @P pointer bump
        }
    }
    g_cntS[slice * NP + q] = (int)((ptr - base) / NP);  // >SUBCAP -> ovf flag
}

// ---- knn final: warp-per-slice cooperative exact top-20 ----
// Block: 256 threads = 8 warps x 32 lanes; warp w = slice w, lane = query.
// Phase 1: per-thread local top-22 of its slice (global top-22 incl self is
//          contained in the union of per-slice top-22s).
// Phase 2: slice-0 threads merge 8x22 smem scores -> t21 (21st excl self;
//          self = strict max absorbs the extra slot).
// Phase 3: count survivors > t21 per slice, smem prefix -> disjoint writes.
//          g_knn order is irrelevant (max-pool); ties/overflow -> exact fallback.
__global__ void knn_final_kernel() {
    __shared__ float sS[NSLICE][32][23];    // padded: stride 23 is odd -> no conflicts
    __shared__ int   sCnt[NSLICE][32];
    __shared__ float sT[32];

    const int lane = threadIdx.x & 31;
    const int sl   = threadIdx.x >> 5;
    const int q    = blockIdx.x * 32 + lane;
    const float NEG = -3.0e38f;

    int c = g_cntS[sl * NP + q];
    const bool ovf = (c > SUBCAP);
    if (c > SUBCAP) c = SUBCAP;
    const unsigned long long* myb = &g_buf[(size_t)(sl * SUBCAP) * NP + q];

    float ss[22];
#pragma unroll
    for (int t = 0; t < 22; t++) ss[t] = NEG;
    {
        int m = 0;
        for (; m + 4 <= c; m += 4) {                  // coalesced, MLP=4
            unsigned long long e0 = myb[(m+0) * NP];
            unsigned long long e1 = myb[(m+1) * NP];
            unsigned long long e2 = myb[(m+2) * NP];
            unsigned long long e3 = myb[(m+3) * NP];
            merge22(ss, scoreOf(e0));
            merge22(ss, scoreOf(e1));
            merge22(ss, scoreOf(e2));
            merge22(ss, scoreOf(e3));
        }
        for (; m < c; m++) merge22(ss, scoreOf(myb[m * NP]));
    }
#pragma unroll
    for (int t = 0; t < 22; t++) sS[sl][lane][t] = ss[t];
    __syncthreads();

    // phase 2: slice-0 threads merge the other 7 lists
    if (sl == 0) {
        for (int s2 = 1; s2 < NSLICE; s2++)
#pragma unroll
            for (int t = 0; t < 22; t++) merge22(ss, sS[s2][lane][t]);
        sT[lane] = ss[0];                             // 21st best excluding self
    }
    __syncthreads();
    const float t21 = sT[lane];

    // phase 3: count survivors strictly above t21 in my slice
    int na = 0;
    for (int m = 0; m < c; m++) {
        unsigned long long e = myb[m * NP];
        na += (scoreOf(e) > t21 && idxOf(e) != q) ? 1 : 0;
    }
    if (ovf) na = 1 << 20;                            // force fallback on overflow
    sCnt[sl][lane] = na;
    __syncthreads();

    int pre = 0, total = 0;
    for (int s2 = 0; s2 < NSLICE; s2++) {
        int v = sCnt[s2][lane];
        pre += (s2 < sl) ? v : 0;
        total += v;
    }

    if (total == KK) {                                // common case: exact, no ties
        int o = pre;
        for (int m = 0; m < c; m++) {
            unsigned long long e = myb[m * NP];
            int j = idxOf(e);
            if (scoreOf(e) > t21 && j != q) g_knn[q*KK + (o++)] = j;
        }
    } else if (sl == 0) {                             // P~0: ties or overflow
        const float4 me = g_cand[q];
        float bs[21];
#pragma unroll
        for (int t = 0; t < 21; t++) bs[t] = NEG;
        for (int j = 0; j < NP; j++)
            merge21(bs, (j != q) ? scoreQ(me, g_cand[j]) : NEG);
        float b21 = bs[0];
        int out = 0;
        for (int j = 0; j < NP && out < KK; j++)
            if (j != q && scoreQ(me, g_cand[j]) > b21) g_knn[q*KK + (out++)] = j;
        for (int j = 0; j < NP && out < KK; j++)
            if (j != q && scoreQ(me, g_cand[j]) == b21) g_knn[q*KK + (out++)] = j;
    }
}

// ---- SGEMM: AB[16384,512] = X[16384,128] @ W2[128,512]  (+bias on cols<256) ----
// Inner product via packed fma.rn.f32x2: 32 FFMA2 per k-step instead of 64 FFMA.
__global__ void gemm_kernel(const float* __restrict__ X, const float* __restrict__ bias) {
    __shared__ __align__(16) float As[8][128];
    __shared__ __align__(16) float Bs[8][128];
    const int tid = threadIdx.x;
    const int m0 = blockIdx.y * 128;
    const int n0 = blockIdx.x * 128;
    const int tx = tid & 15;
    const int ty = tid >> 4;
    const int lam = tid >> 1;
    const int lak = (tid & 1) * 4;
    const int lbr = tid >> 5;
    const int lbc = (tid & 31) * 4;

    unsigned long long acc[8][4];
#pragma unroll
    for (int i = 0; i < 8; i++)
#pragma unroll
        for (int j = 0; j < 4; j++) acc[i][j] = 0ull;

    for (int kb = 0; kb < CIN; kb += 8) {
        float4 av = *(const float4*)&X[(size_t)(m0 + lam)*CIN + kb + lak];
        float4 bv = *(const float4*)&g_W2[(kb + lbr)*WCOLS + n0 + lbc];
        __syncthreads();
        As[lak+0][lam] = av.x;
        As[lak+1][lam] = av.y;
        As[lak+2][lam] = av.z;
        As[lak+3][lam] = av.w;
        *(float4*)&Bs[lbr][lbc] = bv;
        __syncthreads();
#pragma unroll
        for (int k = 0; k < 8; k++) {
            float a[8];
            *(float4*)&a[0] = *(const float4*)&As[k][ty*8];
            *(float4*)&a[4] = *(const float4*)&As[k][ty*8 + 4];
            unsigned long long b2[4];
            const unsigned long long* bp = (const unsigned long long*)&Bs[k][tx*8];
            b2[0] = bp[0]; b2[1] = bp[1]; b2[2] = bp[2]; b2[3] = bp[3];
#pragma unroll
            for (int i = 0; i < 8; i++) {
                unsigned long long a2 = bcast2(a[i]);
#pragma unroll
                for (int j = 0; j < 4; j++)
                    acc[i][j] = ffma2(a2, b2[j], acc[i][j]);
            }
        }
    }
    const bool addb = (n0 < COUT);
#pragma unroll
    for (int i = 0; i < 8; i++) {
        int row = m0 + ty*8 + i;
        float r[8];
#pragma unroll
        for (int j = 0; j < 4; j++) unpack2(acc[i][j], r[2*j], r[2*j+1]);
#pragma unroll
        for (int j = 0; j < 8; j += 4) {
            int col = n0 + tx*8 + j;
            float4 v;
            v.x = r[j+0] + (addb ? bias[col+0] : 0.0f);
            v.y = r[j+1] + (addb ? bias[col+1] : 0.0f);
            v.z = r[j+2] + (addb ? bias[col+2] : 0.0f);
            v.w = r[j+3] + (addb ? bias[col+3] : 0.0f);
            *(float4*)&g_AB[(size_t)row*WCOLS + col] = v;
        }
    }
}

// ---- fused edge pass: 2 channels/thread, per (i,c) extreme + channel sum/sumsq ----
__global__ void edge_kernel(const float* __restrict__ gamma) {
    const int c2 = threadIdx.x;            // 0..127 -> channels 2*c2, 2*c2+1
    const int c0 = 2*c2;
    const int i0 = blockIdx.x * QPB;
    const bool uM0 = (gamma[c0]   >= 0.0f);
    const bool uM1 = (gamma[c0+1] >= 0.0f);
    float ps0 = 0.f, ps1 = 0.f, pq0 = 0.f, pq1 = 0.f;
    for (int g = 0; g < QPB; g++) {
        const int i = i0 + g;
        float2 a = *(const float2*)&g_AB[(size_t)i*WCOLS + c0];
        float b0 = uM0 ? -3.0e38f : 3.0e38f;
        float b1 = uM1 ? -3.0e38f : 3.0e38f;
#pragma unroll
        for (int k = 0; k < KK; k++) {
            int j = g_knn[i*KK + k];
            float2 bv = *(const float2*)&g_AB[(size_t)j*WCOLS + COUT + c0];
            float h0 = a.x + bv.x;
            float h1 = a.y + bv.y;
            ps0 += h0; pq0 = fmaf(h0, h0, pq0);
            ps1 += h1; pq1 = fmaf(h1, h1, pq1);
            b0 = uM0 ? fmaxf(b0, h0) : fminf(b0, h0);
            b1 = uM1 ? fmaxf(b1, h1) : fminf(b1, h1);
        }
        *(float2*)&g_sel[(size_t)i*COUT + c0] = make_float2(b0, b1);
    }
    atomicAdd(&g_sumD[c0],     (double)ps0);
    atomicAdd(&g_sumD[c0+1],   (double)ps1);
    atomicAdd(&g_sumsqD[c0],   (double)pq0);
    atomicAdd(&g_sumsqD[c0+1], (double)pq1);
}

// ---- BN stats -> per-channel scale/shift ----
__global__ void finalize_kernel(const float* __restrict__ gamma, const float* __restrict__ beta) {
    int c = threadIdx.x;
    const double inv = 1.0 / (double)(NP * KK);
    double m  = g_sumD[c] * inv;
    double v  = g_sumsqD[c] * inv - m*m;
    float sc = gamma[c] * rsqrtf((float)v + 1e-5f);
    g_scale[c] = sc;
    g_shift[c] = beta[c] - (float)m * sc;
}

// ---- epilogue: normalize selected extreme + LeakyReLU ----
__global__ void out_kernel(float* __restrict__ out) {
    int t = blockIdx.x * blockDim.x + threadIdx.x;
    int c = t & (COUT - 1);
    float h = fmaf(g_sel[t], g_scale[c], g_shift[c]);
    out[t] = (h >= 0.0f) ? h : 0.2f*h;
}

extern "C" void kernel_launch(void* const* d_in, const int* in_sizes, int n_in,
                              void* d_out, int out_size) {
    const float* pos   = (const float*)d_in[0];
    const float* x     = (const float*)d_in[1];
    const float* W     = (const float*)d_in[2];
    const float* b     = (const float*)d_in[3];
    const float* gamma = (const float*)d_in[4];
    const float* beta  = (const float*)d_in[5];
    float* out = (float*)d_out;

    prep_kernel<<<256, 256>>>(pos, W);                         // 0
    knn_thresh_kernel<<<NP / 256, 256>>>();                    // 1
    gemm_kernel<<<dim3(WCOLS / 128, NP / 128), 256>>>(x, b);   // 2
    knn_filter_kernel<<<dim3(NP / 256, NSLICE), 256>>>();      // 3 (ncu slot)
    knn_final_kernel<<<NP / 32, 256>>>();                      // 4
    edge_kernel<<<NP / QPB, 128>>>(gamma);                     // 5
    finalize_kernel<<<1, COUT>>>(gamma, beta);                 // 6
    out_kernel<<<(NP * COUT) / 256, 256>>>(out);               // 7
}